// round 11
// baseline (speedup 1.0000x reference)
#include <cuda_runtime.h>
#include <cuda_bf16.h>
#include <cstdint>

// Problem constants
#define BATCH 2
#define SEQ 2048
#define HID 3584
#define NH 28
#define NKV 4
#define HD 128
#define NREP 7
#define M_ROWS (BATCH * SEQ)           // 4096
#define KV_HID (NKV * HD)              // 512
#define SCALE_F 0.08838834764831845f   // 128^-0.5

// Scratch (device globals; allocation is forbidden)
__device__ float g_Q[(size_t)M_ROWS * HID];
__device__ float g_K[(size_t)M_ROWS * KV_HID];
__device__ float g_V[(size_t)M_ROWS * KV_HID];
__device__ float g_A[(size_t)M_ROWS * HID];
__device__ __nv_bfloat16 g_Qhi[(size_t)M_ROWS * HID];
__device__ __nv_bfloat16 g_Qlo[(size_t)M_ROWS * HID];
__device__ __nv_bfloat16 g_Khi[(size_t)M_ROWS * KV_HID];
__device__ __nv_bfloat16 g_Klo[(size_t)M_ROWS * KV_HID];
// tf32-rounded (rna) weight copies (A-side rounding happens in-loop)
__device__ float g_QWr[(size_t)HID * HID];
__device__ float g_KWr[(size_t)KV_HID * HID];
__device__ float g_VWr[(size_t)KV_HID * HID];
__device__ float g_OWr[(size_t)HID * HID];

// ---------------------------------------------------------------------------
// Helpers
// ---------------------------------------------------------------------------
__device__ __forceinline__ float to_tf32(float x) {
    asm("cvt.rna.tf32.f32 %0, %0;" : "+f"(x));
    return x;
}
__device__ __forceinline__ uint32_t rna_u(uint32_t x) {
    float f = __uint_as_float(x);
    asm("cvt.rna.tf32.f32 %0, %0;" : "+f"(f));
    return __float_as_uint(f);
}
__device__ __forceinline__ void ldmx4(uint32_t& r0, uint32_t& r1, uint32_t& r2,
                                      uint32_t& r3, uint32_t addr) {
    asm volatile("ldmatrix.sync.aligned.m8n8.x4.shared.b16 {%0,%1,%2,%3}, [%4];"
                 : "=r"(r0), "=r"(r1), "=r"(r2), "=r"(r3) : "r"(addr));
}
__device__ __forceinline__ void mma_tf32(float* c, const uint32_t* a,
                                         uint32_t b0, uint32_t b1) {
    asm volatile(
        "mma.sync.aligned.m16n8k8.row.col.f32.tf32.tf32.f32 "
        "{%0,%1,%2,%3}, {%4,%5,%6,%7}, {%8,%9}, {%0,%1,%2,%3};"
        : "+f"(c[0]), "+f"(c[1]), "+f"(c[2]), "+f"(c[3])
        : "r"(a[0]), "r"(a[1]), "r"(a[2]), "r"(a[3]), "r"(b0), "r"(b1));
}
__device__ __forceinline__ void mma_tf32f(float* c, const float* a,
                                          float b0f, float b1f) {
    uint32_t a0 = __float_as_uint(a[0]), a1 = __float_as_uint(a[1]);
    uint32_t a2 = __float_as_uint(a[2]), a3 = __float_as_uint(a[3]);
    uint32_t b0 = __float_as_uint(b0f), b1 = __float_as_uint(b1f);
    asm volatile(
        "mma.sync.aligned.m16n8k8.row.col.f32.tf32.tf32.f32 "
        "{%0,%1,%2,%3}, {%4,%5,%6,%7}, {%8,%9}, {%0,%1,%2,%3};"
        : "+f"(c[0]), "+f"(c[1]), "+f"(c[2]), "+f"(c[3])
        : "r"(a0), "r"(a1), "r"(a2), "r"(a3), "r"(b0), "r"(b1));
}
__device__ __forceinline__ void mma_bf16(float* c, const uint32_t* a,
                                         uint32_t b0, uint32_t b1) {
    asm volatile(
        "mma.sync.aligned.m16n8k16.row.col.f32.bf16.bf16.f32 "
        "{%0,%1,%2,%3}, {%4,%5,%6,%7}, {%8,%9}, {%0,%1,%2,%3};"
        : "+f"(c[0]), "+f"(c[1]), "+f"(c[2]), "+f"(c[3])
        : "r"(a[0]), "r"(a[1]), "r"(a[2]), "r"(a[3]), "r"(b0), "r"(b1));
}
__device__ __forceinline__ void cp16(uint32_t dst, const void* src) {
    asm volatile("cp.async.cg.shared.global [%0], [%1], 16;" :: "r"(dst), "l"(src));
}
__device__ __forceinline__ void cp_commit() {
    asm volatile("cp.async.commit_group;");
}
template <int N>
__device__ __forceinline__ void cp_wait() {
    asm volatile("cp.async.wait_group %0;" :: "n"(N));
}
__device__ __forceinline__ void bsplit(float x, __nv_bfloat16& hi, __nv_bfloat16& lo) {
    hi = __float2bfloat16(x);
    lo = __float2bfloat16(x - __bfloat162float(hi));
}

// ---------------------------------------------------------------------------
// Elementwise tf32 (rna) rounding pass (weights only; off critical path)
// ---------------------------------------------------------------------------
__global__ void round_tf32_k(const float4* __restrict__ in, float4* __restrict__ out, int n4)
{
    const int i = blockIdx.x * blockDim.x + threadIdx.x;
    if (i < n4) {
        float4 v = in[i];
        v.x = to_tf32(v.x); v.y = to_tf32(v.y);
        v.z = to_tf32(v.z); v.w = to_tf32(v.w);
        out[i] = v;
    }
}

// ---------------------------------------------------------------------------
// TF32 tensor-core GEMM: C[M,N] = A[M,K] @ W[N,K]^T + bias
// W PRE-ROUNDED to tf32; A rounded in-loop if rndA (bit-identical to
// pre-rounded array). 128x128 tile, BK=16, 256 threads, 3-stage cp.async
// pipeline (STATIC smem — proven 2 CTAs/SM).
// ---------------------------------------------------------------------------
#define LDA 20
#define BUF_FLOATS (128 * LDA)
#define BUF_BYTES (BUF_FLOATS * 4)

__global__ void __launch_bounds__(256, 2) tf32_gemm_nt(
    const float* __restrict__ A, const float* __restrict__ W,
    const float* __restrict__ bias, float* __restrict__ C,
    int M, int N, int K, int rnd, int rndA)
{
    __shared__ __align__(16) float As[3][BUF_FLOATS];
    __shared__ __align__(16) float Bs[3][BUF_FLOATS];

    const int bm = blockIdx.y * 128;
    const int bn = blockIdx.x * 128;
    const int tid = threadIdx.x;
    const int lane = tid & 31;
    const int wid = tid >> 5;
    const int wm = wid >> 2;
    const int wn = wid & 3;
    const int g = lane >> 3;
    const int lr = lane & 7;

    const uint32_t sA = (uint32_t)__cvta_generic_to_shared(&As[0][0]);
    const uint32_t sB = (uint32_t)__cvta_generic_to_shared(&Bs[0][0]);

    uint32_t aBase[4], bBase[2];
#pragma unroll
    for (int m = 0; m < 4; m++) {
        int row = wm * 64 + m * 16 + lr + (g & 1) * 8;
        int col = (g >> 1) * 4;
        aBase[m] = sA + (row * LDA + col) * 4;
    }
#pragma unroll
    for (int p = 0; p < 2; p++) {
        int row = wn * 32 + p * 16 + lr + (g >> 1) * 8;
        int col = (g & 1) * 4;
        bBase[p] = sB + (row * LDA + col) * 4;
    }

    const int lrow = tid >> 2;
    const int lcol = (tid & 3) << 2;
    const float* Ap = A + (size_t)(bm + lrow) * K + lcol;
    const float* Wp = W + (size_t)(bn + lrow) * K + lcol;
    const uint32_t smoff = (lrow * LDA + lcol) * 4;
    const uint32_t smoff2 = smoff + 64 * LDA * 4;

    auto issue = [&](int t, int s) {
        const uint32_t da = sA + (uint32_t)s * BUF_BYTES;
        const uint32_t db = sB + (uint32_t)s * BUF_BYTES;
        const float* ap = Ap + t * 16;
        const float* wp = Wp + t * 16;
        cp16(da + smoff, ap);
        cp16(da + smoff2, ap + (size_t)64 * K);
        cp16(db + smoff, wp);
        cp16(db + smoff2, wp + (size_t)64 * K);
        cp_commit();
    };

    float acc[4][4][4];
#pragma unroll
    for (int m = 0; m < 4; m++)
#pragma unroll
        for (int n = 0; n < 4; n++)
#pragma unroll
            for (int i = 0; i < 4; i++) acc[m][n][i] = 0.f;

    const int T = K / 16;
    issue(0, 0);
    issue(1, 1);

    for (int t = 0; t < T; t++) {
        if (t + 1 < T) cp_wait<1>(); else cp_wait<0>();
        __syncthreads();
        if (t + 2 < T) issue(t + 2, (t + 2) % 3);

        const uint32_t bufoff = (uint32_t)(t % 3) * BUF_BYTES;
#pragma unroll
        for (int ks = 0; ks < 16; ks += 8) {
            uint32_t afr[4][4];
#pragma unroll
            for (int m = 0; m < 4; m++) {
                ldmx4(afr[m][0], afr[m][1], afr[m][2], afr[m][3],
                      aBase[m] + bufoff + ks * 4);
                if (rndA) {
                    afr[m][0] = rna_u(afr[m][0]); afr[m][1] = rna_u(afr[m][1]);
                    afr[m][2] = rna_u(afr[m][2]); afr[m][3] = rna_u(afr[m][3]);
                }
            }
#pragma unroll
            for (int p = 0; p < 2; p++) {
                uint32_t bf0, bf1, bf2, bf3;
                ldmx4(bf0, bf1, bf2, bf3, bBase[p] + bufoff + ks * 4);
#pragma unroll
                for (int m = 0; m < 4; m++) {
                    mma_tf32(acc[m][2 * p + 0], afr[m], bf0, bf1);
                    mma_tf32(acc[m][2 * p + 1], afr[m], bf2, bf3);
                }
            }
        }
    }

#pragma unroll
    for (int m = 0; m < 4; m++) {
        const int row = bm + wm * 64 + m * 16 + (lane >> 2);
#pragma unroll
        for (int n = 0; n < 4; n++) {
            const int col = bn + wn * 32 + n * 8 + (lane & 3) * 2;
            float bx = 0.f, by = 0.f;
            if (bias) { bx = bias[col]; by = bias[col + 1]; }
            float2 v0 = make_float2(acc[m][n][0] + bx, acc[m][n][1] + by);
            float2 v1 = make_float2(acc[m][n][2] + bx, acc[m][n][3] + by);
            if (rnd) {
                v0.x = to_tf32(v0.x); v0.y = to_tf32(v0.y);
                v1.x = to_tf32(v1.x); v1.y = to_tf32(v1.y);
            }
            *(float2*)&C[(size_t)row * N + col] = v0;
            *(float2*)&C[(size_t)(row + 8) * N + col] = v1;
        }
    }
}

// ---------------------------------------------------------------------------
// RoPE + bf16 hi/lo split. Q additionally prescaled by SCALE_F.
// ---------------------------------------------------------------------------
__global__ void rope_split(const float* __restrict__ Q, const float* __restrict__ K,
                           const float* __restrict__ cosT, const float* __restrict__ sinT,
                           __nv_bfloat16* __restrict__ Qh, __nv_bfloat16* __restrict__ Ql,
                           __nv_bfloat16* __restrict__ Kh, __nv_bfloat16* __restrict__ Kl)
{
    const int idx = blockIdx.x * blockDim.x + threadIdx.x;
    const int d = idx & 63;
    const int h = (idx >> 6) & 31;
    const int s = (idx >> 11) & 2047;
    const int b = idx >> 22;

    const float c1 = cosT[s * 128 + d];
    const float s1 = sinT[s * 128 + d];
    const float c2 = cosT[s * 128 + d + 64];
    const float s2 = sinT[s * 128 + d + 64];

    if (h < 28) {
        const size_t base = (((size_t)b * SEQ + s) * NH + h) * HD;
        const float x1 = Q[base + d];
        const float x2 = Q[base + d + 64];
        const float r1 = (x1 * c1 - x2 * s1) * SCALE_F;
        const float r2 = (x2 * c2 + x1 * s2) * SCALE_F;
        __nv_bfloat16 hi, lo;
        bsplit(r1, hi, lo); Qh[base + d] = hi; Ql[base + d] = lo;
        bsplit(r2, hi, lo); Qh[base + d + 64] = hi; Ql[base + d + 64] = lo;
    } else {
        const size_t base = (((size_t)b * SEQ + s) * NKV + (h - 28)) * HD;
        const float x1 = K[base + d];
        const float x2 = K[base + d + 64];
        const float r1 = x1 * c1 - x2 * s1;
        const float r2 = x2 * c2 + x1 * s2;
        __nv_bfloat16 hi, lo;
        bsplit(r1, hi, lo); Kh[base + d] = hi; Kl[base + d] = lo;
        bsplit(r2, hi, lo); Kh[base + d + 64] = hi; Kl[base + d + 64] = lo;
    }
}

// ---------------------------------------------------------------------------
// Tensor-core causal flash attention (bf16-split QK + tf32 PV).
// Single launch over both batches; longest-first CTA order.
// ---------------------------------------------------------------------------
#define QB 128
#define KB 64
#define FL_QL 34816
#define FL_ST 69632
#define FL_STSZ 69632
#define FL_KL 17408
#define FL_V  34816
#define FL_SMEM 208896
#define LDV 136

__global__ void __launch_bounds__(256, 1) flash_tc(
    const __nv_bfloat16* __restrict__ Qh, const __nv_bfloat16* __restrict__ Ql,
    const __nv_bfloat16* __restrict__ Kh, const __nv_bfloat16* __restrict__ Kl,
    const float* __restrict__ V, float* __restrict__ O)
{
    extern __shared__ char smc[];
    const uint32_t sb = (uint32_t)__cvta_generic_to_shared(smc);

    const int qb = gridDim.x - 1 - blockIdx.x;   // longest-first
    const int h = blockIdx.y, b = blockIdx.z;
    const int kvh = h / NREP;
    const int tid = threadIdx.x;
    const int lane = tid & 31;
    const int w = tid >> 5;
    const int q4 = lane & 3;
    const int r4 = lane >> 2;

    {
        const char* qhg = (const char*)(Qh + (((size_t)b * SEQ + (size_t)qb * QB) * NH + h) * HD);
        const char* qlg = (const char*)(Ql + (((size_t)b * SEQ + (size_t)qb * QB) * NH + h) * HD);
#pragma unroll
        for (int i = 0; i < 16; i++) {
            const int id = tid + i * 256;
            if (id < 2048) {
                const int row = id >> 4, off = (id & 15) * 16;
                cp16(sb + row * 272 + off, qhg + (size_t)row * (NH * HD * 2) + off);
            } else {
                const int id2 = id - 2048;
                const int row = id2 >> 4, off = (id2 & 15) * 16;
                cp16(sb + FL_QL + row * 272 + off, qlg + (size_t)row * (NH * HD * 2) + off);
            }
        }
        cp_commit();
    }

    const char* khg0 = (const char*)(Kh + ((size_t)b * SEQ) * KV_HID + kvh * HD);
    const char* klg0 = (const char*)(Kl + ((size_t)b * SEQ) * KV_HID + kvh * HD);
    const char* vg0  = (const char*)(V + ((size_t)b * SEQ) * KV_HID + kvh * HD);

    auto issue_kv = [&](int kb, int s) {
        const uint32_t stb = sb + FL_ST + (uint32_t)s * FL_STSZ;
        const char* khg = khg0 + (size_t)kb * KB * 1024;
        const char* klg = klg0 + (size_t)kb * KB * 1024;
        const char* vg  = vg0 + (size_t)kb * KB * 2048;
#pragma unroll
        for (int i = 0; i < 16; i++) {
            const int id = tid + i * 256;
            if (id < 1024) {
                const int row = id >> 4, off = (id & 15) * 16;
                cp16(stb + row * 272 + off, khg + (size_t)row * 1024 + off);
            } else if (id < 2048) {
                const int id2 = id - 1024;
                const int row = id2 >> 4, off = (id2 & 15) * 16;
                cp16(stb + FL_KL + row * 272 + off, klg + (size_t)row * 1024 + off);
            } else {
                const int id2 = id - 2048;
                const int row = id2 >> 5, off = (id2 & 31) * 16;
                cp16(stb + FL_V + row * 544 + off, vg + (size_t)row * 2048 + off);
            }
        }
        cp_commit();
    };

    const int kbmax = 2 * qb + 1;
    issue_kv(0, 0);
    issue_kv(1, 1);

    float oacc[16][4];
#pragma unroll
    for (int i = 0; i < 16; i++)
#pragma unroll
        for (int c = 0; c < 4; c++) oacc[i][c] = 0.f;
    float m0 = -1e30f, m1 = -1e30f, l0 = 0.f, l1 = 0.f;

    const int arow = w * 16 + r4;
    const int rg0 = qb * QB + arow;
    const int rg1 = rg0 + 8;

    const char* aH = smc + arow * 272 + q4 * 4;
    const char* aL = smc + FL_QL + arow * 272 + q4 * 4;

    for (int kb = 0; kb <= kbmax; kb++) {
        if (kb < kbmax) cp_wait<1>(); else cp_wait<0>();
        __syncthreads();

        const int cur = kb & 1;
        const char* Khp = smc + FL_ST + (size_t)cur * FL_STSZ;
        const char* Klp = Khp + FL_KL;
        const float* Vsp = (const float*)(Khp + FL_V);

        float sacc[8][4];
#pragma unroll
        for (int nt = 0; nt < 8; nt++)
#pragma unroll
            for (int c = 0; c < 4; c++) sacc[nt][c] = 0.f;

#pragma unroll
        for (int kt = 0; kt < 8; kt++) {
            const int ko = kt * 32;
            uint32_t ah[4], al[4];
            ah[0] = *(const uint32_t*)(aH + ko);
            ah[1] = *(const uint32_t*)(aH + ko + 8 * 272);
            ah[2] = *(const uint32_t*)(aH + ko + 16);
            ah[3] = *(const uint32_t*)(aH + ko + 8 * 272 + 16);
            al[0] = *(const uint32_t*)(aL + ko);
            al[1] = *(const uint32_t*)(aL + ko + 8 * 272);
            al[2] = *(const uint32_t*)(aL + ko + 16);
            al[3] = *(const uint32_t*)(aL + ko + 8 * 272 + 16);
#pragma unroll
            for (int nt = 0; nt < 8; nt++) {
                const char* bp = Khp + (nt * 8 + r4) * 272 + q4 * 4 + ko;
                const char* bq = Klp + (nt * 8 + r4) * 272 + q4 * 4 + ko;
                const uint32_t bh0 = *(const uint32_t*)bp;
                const uint32_t bh1 = *(const uint32_t*)(bp + 16);
                const uint32_t bl0 = *(const uint32_t*)bq;
                const uint32_t bl1 = *(const uint32_t*)(bq + 16);
                mma_bf16(sacc[nt], ah, bh0, bh1);
                mma_bf16(sacc[nt], al, bh0, bh1);
                mma_bf16(sacc[nt], ah, bl0, bl1);
            }
        }

        if (kb >= 2 * qb) {
            const int colb = kb * KB + 2 * q4;
#pragma unroll
            for (int nt = 0; nt < 8; nt++) {
                const int c0 = colb + nt * 8;
                if (c0 > rg0)     sacc[nt][0] = -1e30f;
                if (c0 + 1 > rg0) sacc[nt][1] = -1e30f;
                if (c0 > rg1)     sacc[nt][2] = -1e30f;
                if (c0 + 1 > rg1) sacc[nt][3] = -1e30f;
            }
        }
        float mb0 = -1e30f, mb1 = -1e30f;
#pragma unroll
        for (int nt = 0; nt < 8; nt++) {
            mb0 = fmaxf(mb0, fmaxf(sacc[nt][0], sacc[nt][1]));
            mb1 = fmaxf(mb1, fmaxf(sacc[nt][2], sacc[nt][3]));
        }
        mb0 = fmaxf(mb0, __shfl_xor_sync(0xffffffffu, mb0, 1));
        mb0 = fmaxf(mb0, __shfl_xor_sync(0xffffffffu, mb0, 2));
        mb1 = fmaxf(mb1, __shfl_xor_sync(0xffffffffu, mb1, 1));
        mb1 = fmaxf(mb1, __shfl_xor_sync(0xffffffffu, mb1, 2));

        const float mn0 = fmaxf(m0, mb0), mn1 = fmaxf(m1, mb1);
        const float a0 = __expf(m0 - mn0), a1 = __expf(m1 - mn1);
        m0 = mn0; m1 = mn1;

        float ls0 = 0.f, ls1 = 0.f;
#pragma unroll
        for (int nt = 0; nt < 8; nt++) {
            float p0 = to_tf32(__expf(sacc[nt][0] - mn0));
            float p1 = to_tf32(__expf(sacc[nt][1] - mn0));
            float p2 = to_tf32(__expf(sacc[nt][2] - mn1));
            float p3 = to_tf32(__expf(sacc[nt][3] - mn1));
            sacc[nt][0] = p0; sacc[nt][1] = p1;
            sacc[nt][2] = p2; sacc[nt][3] = p3;
            ls0 += p0 + p1; ls1 += p2 + p3;
        }
        ls0 += __shfl_xor_sync(0xffffffffu, ls0, 1);
        ls0 += __shfl_xor_sync(0xffffffffu, ls0, 2);
        ls1 += __shfl_xor_sync(0xffffffffu, ls1, 1);
        ls1 += __shfl_xor_sync(0xffffffffu, ls1, 2);
        l0 = l0 * a0 + ls0;
        l1 = l1 * a1 + ls1;

#pragma unroll
        for (int nt2 = 0; nt2 < 16; nt2++) {
            oacc[nt2][0] *= a0; oacc[nt2][1] *= a0;
            oacc[nt2][2] *= a1; oacc[nt2][3] *= a1;
        }

        const int src0 = (lane & ~3) | (q4 >> 1);
        const int src1 = src0 | 2;
        const bool oddq = (q4 & 1);
#pragma unroll
        for (int kt2 = 0; kt2 < 8; kt2++) {
            const float t00 = __shfl_sync(0xffffffffu, sacc[kt2][0], src0);
            const float t01 = __shfl_sync(0xffffffffu, sacc[kt2][1], src0);
            const float t02 = __shfl_sync(0xffffffffu, sacc[kt2][2], src0);
            const float t03 = __shfl_sync(0xffffffffu, sacc[kt2][3], src0);
            const float t10 = __shfl_sync(0xffffffffu, sacc[kt2][0], src1);
            const float t11 = __shfl_sync(0xffffffffu, sacc[kt2][1], src1);
            const float t12 = __shfl_sync(0xffffffffu, sacc[kt2][2], src1);
            const float t13 = __shfl_sync(0xffffffffu, sacc[kt2][3], src1);
            float pa[4];
            pa[0] = oddq ? t01 : t00;
            pa[1] = oddq ? t03 : t02;
            pa[2] = oddq ? t11 : t10;
            pa[3] = oddq ? t13 : t12;
            const float* vrow = Vsp + (kt2 * 8 + q4) * LDV + r4;
#pragma unroll
            for (int nt2 = 0; nt2 < 16; nt2++) {
                mma_tf32f(oacc[nt2], pa, vrow[nt2 * 8], vrow[nt2 * 8 + 4 * LDV]);
            }
        }

        __syncthreads();
        if (kb + 2 <= kbmax) issue_kv(kb + 2, cur);
    }

    const float inv0 = 1.f / l0, inv1 = 1.f / l1;
    float* o0 = O + (((size_t)b * SEQ + rg0) * NH + h) * HD;
    float* o1 = O + (((size_t)b * SEQ + rg1) * NH + h) * HD;
#pragma unroll
    for (int nt2 = 0; nt2 < 16; nt2++) {
        const int col = nt2 * 8 + 2 * q4;
        *(float2*)(o0 + col) = make_float2(to_tf32(oacc[nt2][0] * inv0),
                                           to_tf32(oacc[nt2][1] * inv0));
        *(float2*)(o1 + col) = make_float2(to_tf32(oacc[nt2][2] * inv1),
                                           to_tf32(oacc[nt2][3] * inv1));
    }
}

// ---------------------------------------------------------------------------
extern "C" void kernel_launch(void* const* d_in, const int* in_sizes, int n_in,
                              void* d_out, int out_size)
{
    const float* hs   = (const float*)d_in[0];
    const float* cosT = (const float*)d_in[1];
    const float* sinT = (const float*)d_in[2];
    const float* q_w = (const float*)d_in[4];
    const float* q_b = (const float*)d_in[5];
    const float* k_w = (const float*)d_in[6];
    const float* k_b = (const float*)d_in[7];
    const float* v_w = (const float*)d_in[8];
    const float* v_b = (const float*)d_in[9];
    const float* o_w = (const float*)d_in[10];
    float* out = (float*)d_out;

    float *Qb, *Kb, *Vb, *Ab, *QWr, *KWr, *VWr, *OWr;
    __nv_bfloat16 *Qhi, *Qlo, *Khi, *Klo;
    cudaGetSymbolAddress((void**)&Qb, g_Q);
    cudaGetSymbolAddress((void**)&Kb, g_K);
    cudaGetSymbolAddress((void**)&Vb, g_V);
    cudaGetSymbolAddress((void**)&Ab, g_A);
    cudaGetSymbolAddress((void**)&QWr, g_QWr);
    cudaGetSymbolAddress((void**)&KWr, g_KWr);
    cudaGetSymbolAddress((void**)&VWr, g_VWr);
    cudaGetSymbolAddress((void**)&OWr, g_OWr);
    cudaGetSymbolAddress((void**)&Qhi, g_Qhi);
    cudaGetSymbolAddress((void**)&Qlo, g_Qlo);
    cudaGetSymbolAddress((void**)&Khi, g_Khi);
    cudaGetSymbolAddress((void**)&Klo, g_Klo);

    static cudaStream_t sK = nullptr, sV = nullptr;
    static cudaEvent_t eFork = nullptr, eQW = nullptr,
                       eK = nullptr, eV = nullptr, eOW = nullptr;
    if (!sK) {
        cudaStreamCreateWithFlags(&sK, cudaStreamNonBlocking);
        cudaStreamCreateWithFlags(&sV, cudaStreamNonBlocking);
        cudaEventCreateWithFlags(&eFork, cudaEventDisableTiming);
        cudaEventCreateWithFlags(&eQW, cudaEventDisableTiming);
        cudaEventCreateWithFlags(&eK, cudaEventDisableTiming);
        cudaEventCreateWithFlags(&eV, cudaEventDisableTiming);
        cudaEventCreateWithFlags(&eOW, cudaEventDisableTiming);
        cudaFuncSetAttribute(flash_tc, cudaFuncAttributeMaxDynamicSharedMemorySize, FL_SMEM);
    }

    const int nt = 256;

    // Fork FIRST (capture-legal): side streams join via event from origin.
    cudaEventRecord(eFork, 0);
    cudaStreamWaitEvent(sK, eFork, 0);
    cudaStreamWaitEvent(sV, eFork, 0);

    // sK: round QW -> signal; round KW
    {
        const int n4q = HID * HID / 4;
        round_tf32_k<<<(n4q + nt - 1) / nt, nt, 0, sK>>>((const float4*)q_w, (float4*)QWr, n4q);
        cudaEventRecord(eQW, sK);
        const int n4k = KV_HID * HID / 4;
        round_tf32_k<<<(n4k + nt - 1) / nt, nt, 0, sK>>>((const float4*)k_w, (float4*)KWr, n4k);
    }

    // sV: round VW
    {
        const int n4v = KV_HID * HID / 4;
        round_tf32_k<<<(n4v + nt - 1) / nt, nt, 0, sV>>>((const float4*)v_w, (float4*)VWr, n4v);
    }

    // main: Q-proj (A = raw hs, rounded in-loop; needs QWr)
    cudaStreamWaitEvent(0, eQW, 0);
    tf32_gemm_nt<<<dim3(HID / 128, M_ROWS / 128), 256, 0, 0>>>(
        hs, QWr, q_b, Qb, M_ROWS, HID, HID, 0, 1);

    // sK: K-proj
    tf32_gemm_nt<<<dim3(KV_HID / 128, M_ROWS / 128), 256, 0, sK>>>(
        hs, KWr, k_b, Kb, M_ROWS, KV_HID, HID, 0, 1);
    cudaEventRecord(eK, sK);

    // sV: V-proj (tf32-rounded output), then round OW (overlaps rope+flash)
    tf32_gemm_nt<<<dim3(KV_HID / 128, M_ROWS / 128), 256, 0, sV>>>(
        hs, VWr, v_b, Vb, M_ROWS, KV_HID, HID, 1, 1);
    cudaEventRecord(eV, sV);
    {
        const int n4 = HID * HID / 4;
        round_tf32_k<<<(n4 + nt - 1) / nt, nt, 0, sV>>>((const float4*)o_w, (float4*)OWr, n4);
    }
    cudaEventRecord(eOW, sV);

    // Join K,V for rope
    cudaStreamWaitEvent(0, eK, 0);
    cudaStreamWaitEvent(0, eV, 0);

    // RoPE + bf16 hi/lo split
    rope_split<<<(BATCH * SEQ * 32 * 64) / 256, 256>>>(
        Qb, Kb, cosT, sinT, Qhi, Qlo, Khi, Klo);

    // Flash attention (single launch, epilogue writes tf32-rounded A)
    flash_tc<<<dim3(SEQ / QB, NH, BATCH), 256, FL_SMEM>>>(
        Qhi, Qlo, Khi, Klo, Vb, Ab);

    // Output projection (A already rounded; OW pre-rounded; no in-loop cvt)
    cudaStreamWaitEvent(0, eOW, 0);
    tf32_gemm_nt<<<dim3(HID / 128, M_ROWS / 128), 256>>>(
        Ab, OWr, nullptr, out, M_ROWS, HID, HID, 0, 0);
}

// round 12
// speedup vs baseline: 1.1631x; 1.1631x over previous
#include <cuda_runtime.h>
#include <cuda_bf16.h>
#include <cstdint>

// Problem constants
#define BATCH 2
#define SEQ 2048
#define HID 3584
#define NH 28
#define NKV 4
#define HD 128
#define NREP 7
#define M_ROWS (BATCH * SEQ)           // 4096
#define KV_HID (NKV * HD)              // 512
#define SCALE_F 0.08838834764831845f   // 128^-0.5

// Scratch (device globals; allocation is forbidden)
__device__ float g_Q[(size_t)M_ROWS * HID];
__device__ float g_K[(size_t)M_ROWS * KV_HID];
__device__ float g_V[(size_t)M_ROWS * KV_HID];
__device__ float g_A[(size_t)M_ROWS * HID];
__device__ __nv_bfloat16 g_Qhi[(size_t)M_ROWS * HID];
__device__ __nv_bfloat16 g_Qlo[(size_t)M_ROWS * HID];
__device__ __nv_bfloat16 g_Khi[(size_t)M_ROWS * KV_HID];
__device__ __nv_bfloat16 g_Klo[(size_t)M_ROWS * KV_HID];
// tf32-rounded (rna) copies
__device__ float g_HSr[(size_t)M_ROWS * HID];
__device__ float g_QWr[(size_t)HID * HID];
__device__ float g_KWr[(size_t)KV_HID * HID];
__device__ float g_VWr[(size_t)KV_HID * HID];
__device__ float g_OWr[(size_t)HID * HID];

// ---------------------------------------------------------------------------
// Helpers
// ---------------------------------------------------------------------------
__device__ __forceinline__ float to_tf32(float x) {
    asm("cvt.rna.tf32.f32 %0, %0;" : "+f"(x));
    return x;
}
__device__ __forceinline__ void ldmx4(uint32_t& r0, uint32_t& r1, uint32_t& r2,
                                      uint32_t& r3, uint32_t addr) {
    asm volatile("ldmatrix.sync.aligned.m8n8.x4.shared.b16 {%0,%1,%2,%3}, [%4];"
                 : "=r"(r0), "=r"(r1), "=r"(r2), "=r"(r3) : "r"(addr));
}
__device__ __forceinline__ void mma_tf32(float* c, const uint32_t* a,
                                         uint32_t b0, uint32_t b1) {
    asm volatile(
        "mma.sync.aligned.m16n8k8.row.col.f32.tf32.tf32.f32 "
        "{%0,%1,%2,%3}, {%4,%5,%6,%7}, {%8,%9}, {%0,%1,%2,%3};"
        : "+f"(c[0]), "+f"(c[1]), "+f"(c[2]), "+f"(c[3])
        : "r"(a[0]), "r"(a[1]), "r"(a[2]), "r"(a[3]), "r"(b0), "r"(b1));
}
__device__ __forceinline__ void mma_tf32f(float* c, const float* a,
                                          float b0f, float b1f) {
    uint32_t a0 = __float_as_uint(a[0]), a1 = __float_as_uint(a[1]);
    uint32_t a2 = __float_as_uint(a[2]), a3 = __float_as_uint(a[3]);
    uint32_t b0 = __float_as_uint(b0f), b1 = __float_as_uint(b1f);
    asm volatile(
        "mma.sync.aligned.m16n8k8.row.col.f32.tf32.tf32.f32 "
        "{%0,%1,%2,%3}, {%4,%5,%6,%7}, {%8,%9}, {%0,%1,%2,%3};"
        : "+f"(c[0]), "+f"(c[1]), "+f"(c[2]), "+f"(c[3])
        : "r"(a0), "r"(a1), "r"(a2), "r"(a3), "r"(b0), "r"(b1));
}
__device__ __forceinline__ void mma_bf16(float* c, const uint32_t* a,
                                         uint32_t b0, uint32_t b1) {
    asm volatile(
        "mma.sync.aligned.m16n8k16.row.col.f32.bf16.bf16.f32 "
        "{%0,%1,%2,%3}, {%4,%5,%6,%7}, {%8,%9}, {%0,%1,%2,%3};"
        : "+f"(c[0]), "+f"(c[1]), "+f"(c[2]), "+f"(c[3])
        : "r"(a[0]), "r"(a[1]), "r"(a[2]), "r"(a[3]), "r"(b0), "r"(b1));
}
__device__ __forceinline__ void cp16(uint32_t dst, const void* src) {
    asm volatile("cp.async.cg.shared.global [%0], [%1], 16;" :: "r"(dst), "l"(src));
}
__device__ __forceinline__ void cp_commit() {
    asm volatile("cp.async.commit_group;");
}
template <int N>
__device__ __forceinline__ void cp_wait() {
    asm volatile("cp.async.wait_group %0;" :: "n"(N));
}
__device__ __forceinline__ void bsplit(float x, __nv_bfloat16& hi, __nv_bfloat16& lo) {
    hi = __float2bfloat16(x);
    lo = __float2bfloat16(x - __bfloat162float(hi));
}

// ---------------------------------------------------------------------------
// Elementwise tf32 (rna) rounding pass
// ---------------------------------------------------------------------------
__global__ void round_tf32_k(const float4* __restrict__ in, float4* __restrict__ out, int n4)
{
    const int i = blockIdx.x * blockDim.x + threadIdx.x;
    if (i < n4) {
        float4 v = in[i];
        v.x = to_tf32(v.x); v.y = to_tf32(v.y);
        v.z = to_tf32(v.z); v.w = to_tf32(v.w);
        out[i] = v;
    }
}

// ---------------------------------------------------------------------------
// TF32 tensor-core GEMM: C[M,N] = A[M,K] @ W[N,K]^T + bias
// Inputs PRE-ROUNDED to tf32 — NO cvt in the inner loop (R8 config).
// 128x128 tile, BK=16, 256 threads, 3-stage cp.async, 2 CTAs/SM.
// ---------------------------------------------------------------------------
#define LDA 20
#define BUF_FLOATS (128 * LDA)
#define BUF_BYTES (BUF_FLOATS * 4)

__global__ void __launch_bounds__(256, 2) tf32_gemm_nt(
    const float* __restrict__ A, const float* __restrict__ W,
    const float* __restrict__ bias, float* __restrict__ C,
    int M, int N, int K, int rnd)
{
    __shared__ __align__(16) float As[3][BUF_FLOATS];
    __shared__ __align__(16) float Bs[3][BUF_FLOATS];

    const int bm = blockIdx.y * 128;
    const int bn = blockIdx.x * 128;
    const int tid = threadIdx.x;
    const int lane = tid & 31;
    const int wid = tid >> 5;
    const int wm = wid >> 2;
    const int wn = wid & 3;
    const int g = lane >> 3;
    const int lr = lane & 7;

    const uint32_t sA = (uint32_t)__cvta_generic_to_shared(&As[0][0]);
    const uint32_t sB = (uint32_t)__cvta_generic_to_shared(&Bs[0][0]);

    uint32_t aBase[4], bBase[2];
#pragma unroll
    for (int m = 0; m < 4; m++) {
        int row = wm * 64 + m * 16 + lr + (g & 1) * 8;
        int col = (g >> 1) * 4;
        aBase[m] = sA + (row * LDA + col) * 4;
    }
#pragma unroll
    for (int p = 0; p < 2; p++) {
        int row = wn * 32 + p * 16 + lr + (g >> 1) * 8;
        int col = (g & 1) * 4;
        bBase[p] = sB + (row * LDA + col) * 4;
    }

    const int lrow = tid >> 2;
    const int lcol = (tid & 3) << 2;
    const float* Ap = A + (size_t)(bm + lrow) * K + lcol;
    const float* Wp = W + (size_t)(bn + lrow) * K + lcol;
    const uint32_t smoff = (lrow * LDA + lcol) * 4;
    const uint32_t smoff2 = smoff + 64 * LDA * 4;

    auto issue = [&](int t, int s) {
        const uint32_t da = sA + (uint32_t)s * BUF_BYTES;
        const uint32_t db = sB + (uint32_t)s * BUF_BYTES;
        const float* ap = Ap + t * 16;
        const float* wp = Wp + t * 16;
        cp16(da + smoff, ap);
        cp16(da + smoff2, ap + (size_t)64 * K);
        cp16(db + smoff, wp);
        cp16(db + smoff2, wp + (size_t)64 * K);
        cp_commit();
    };

    float acc[4][4][4];
#pragma unroll
    for (int m = 0; m < 4; m++)
#pragma unroll
        for (int n = 0; n < 4; n++)
#pragma unroll
            for (int i = 0; i < 4; i++) acc[m][n][i] = 0.f;

    const int T = K / 16;
    issue(0, 0);
    issue(1, 1);

    for (int t = 0; t < T; t++) {
        if (t + 1 < T) cp_wait<1>(); else cp_wait<0>();
        __syncthreads();
        if (t + 2 < T) issue(t + 2, (t + 2) % 3);

        const uint32_t bufoff = (uint32_t)(t % 3) * BUF_BYTES;
#pragma unroll
        for (int ks = 0; ks < 16; ks += 8) {
            uint32_t afr[4][4];
#pragma unroll
            for (int m = 0; m < 4; m++)
                ldmx4(afr[m][0], afr[m][1], afr[m][2], afr[m][3],
                      aBase[m] + bufoff + ks * 4);
#pragma unroll
            for (int p = 0; p < 2; p++) {
                uint32_t bf0, bf1, bf2, bf3;
                ldmx4(bf0, bf1, bf2, bf3, bBase[p] + bufoff + ks * 4);
#pragma unroll
                for (int m = 0; m < 4; m++) {
                    mma_tf32(acc[m][2 * p + 0], afr[m], bf0, bf1);
                    mma_tf32(acc[m][2 * p + 1], afr[m], bf2, bf3);
                }
            }
        }
    }

#pragma unroll
    for (int m = 0; m < 4; m++) {
        const int row = bm + wm * 64 + m * 16 + (lane >> 2);
#pragma unroll
        for (int n = 0; n < 4; n++) {
            const int col = bn + wn * 32 + n * 8 + (lane & 3) * 2;
            float bx = 0.f, by = 0.f;
            if (bias) { bx = bias[col]; by = bias[col + 1]; }
            float2 v0 = make_float2(acc[m][n][0] + bx, acc[m][n][1] + by);
            float2 v1 = make_float2(acc[m][n][2] + bx, acc[m][n][3] + by);
            if (rnd) {
                v0.x = to_tf32(v0.x); v0.y = to_tf32(v0.y);
                v1.x = to_tf32(v1.x); v1.y = to_tf32(v1.y);
            }
            *(float2*)&C[(size_t)row * N + col] = v0;
            *(float2*)&C[(size_t)(row + 8) * N + col] = v1;
        }
    }
}

// ---------------------------------------------------------------------------
// RoPE + bf16 hi/lo split. Q additionally prescaled by SCALE_F.
// ---------------------------------------------------------------------------
__global__ void rope_split(const float* __restrict__ Q, const float* __restrict__ K,
                           const float* __restrict__ cosT, const float* __restrict__ sinT,
                           __nv_bfloat16* __restrict__ Qh, __nv_bfloat16* __restrict__ Ql,
                           __nv_bfloat16* __restrict__ Kh, __nv_bfloat16* __restrict__ Kl)
{
    const int idx = blockIdx.x * blockDim.x + threadIdx.x;
    const int d = idx & 63;
    const int h = (idx >> 6) & 31;
    const int s = (idx >> 11) & 2047;
    const int b = idx >> 22;

    const float c1 = cosT[s * 128 + d];
    const float s1 = sinT[s * 128 + d];
    const float c2 = cosT[s * 128 + d + 64];
    const float s2 = sinT[s * 128 + d + 64];

    if (h < 28) {
        const size_t base = (((size_t)b * SEQ + s) * NH + h) * HD;
        const float x1 = Q[base + d];
        const float x2 = Q[base + d + 64];
        const float r1 = (x1 * c1 - x2 * s1) * SCALE_F;
        const float r2 = (x2 * c2 + x1 * s2) * SCALE_F;
        __nv_bfloat16 hi, lo;
        bsplit(r1, hi, lo); Qh[base + d] = hi; Ql[base + d] = lo;
        bsplit(r2, hi, lo); Qh[base + d + 64] = hi; Ql[base + d + 64] = lo;
    } else {
        const size_t base = (((size_t)b * SEQ + s) * NKV + (h - 28)) * HD;
        const float x1 = K[base + d];
        const float x2 = K[base + d + 64];
        const float r1 = x1 * c1 - x2 * s1;
        const float r2 = x2 * c2 + x1 * s2;
        __nv_bfloat16 hi, lo;
        bsplit(r1, hi, lo); Kh[base + d] = hi; Kl[base + d] = lo;
        bsplit(r2, hi, lo); Kh[base + d + 64] = hi; Kl[base + d + 64] = lo;
    }
}

// ---------------------------------------------------------------------------
// Tensor-core causal flash attention (bf16-split QK + tf32 PV).
// Single launch over both batches; longest-first CTA order.
// ---------------------------------------------------------------------------
#define QB 128
#define KB 64
#define FL_QL 34816
#define FL_ST 69632
#define FL_STSZ 69632
#define FL_KL 17408
#define FL_V  34816
#define FL_SMEM 208896
#define LDV 136

__global__ void __launch_bounds__(256, 1) flash_tc(
    const __nv_bfloat16* __restrict__ Qh, const __nv_bfloat16* __restrict__ Ql,
    const __nv_bfloat16* __restrict__ Kh, const __nv_bfloat16* __restrict__ Kl,
    const float* __restrict__ V, float* __restrict__ O)
{
    extern __shared__ char smc[];
    const uint32_t sb = (uint32_t)__cvta_generic_to_shared(smc);

    const int qb = gridDim.x - 1 - blockIdx.x;   // longest-first
    const int h = blockIdx.y, b = blockIdx.z;
    const int kvh = h / NREP;
    const int tid = threadIdx.x;
    const int lane = tid & 31;
    const int w = tid >> 5;
    const int q4 = lane & 3;
    const int r4 = lane >> 2;

    {
        const char* qhg = (const char*)(Qh + (((size_t)b * SEQ + (size_t)qb * QB) * NH + h) * HD);
        const char* qlg = (const char*)(Ql + (((size_t)b * SEQ + (size_t)qb * QB) * NH + h) * HD);
#pragma unroll
        for (int i = 0; i < 16; i++) {
            const int id = tid + i * 256;
            if (id < 2048) {
                const int row = id >> 4, off = (id & 15) * 16;
                cp16(sb + row * 272 + off, qhg + (size_t)row * (NH * HD * 2) + off);
            } else {
                const int id2 = id - 2048;
                const int row = id2 >> 4, off = (id2 & 15) * 16;
                cp16(sb + FL_QL + row * 272 + off, qlg + (size_t)row * (NH * HD * 2) + off);
            }
        }
        cp_commit();
    }

    const char* khg0 = (const char*)(Kh + ((size_t)b * SEQ) * KV_HID + kvh * HD);
    const char* klg0 = (const char*)(Kl + ((size_t)b * SEQ) * KV_HID + kvh * HD);
    const char* vg0  = (const char*)(V + ((size_t)b * SEQ) * KV_HID + kvh * HD);

    auto issue_kv = [&](int kb, int s) {
        const uint32_t stb = sb + FL_ST + (uint32_t)s * FL_STSZ;
        const char* khg = khg0 + (size_t)kb * KB * 1024;
        const char* klg = klg0 + (size_t)kb * KB * 1024;
        const char* vg  = vg0 + (size_t)kb * KB * 2048;
#pragma unroll
        for (int i = 0; i < 16; i++) {
            const int id = tid + i * 256;
            if (id < 1024) {
                const int row = id >> 4, off = (id & 15) * 16;
                cp16(stb + row * 272 + off, khg + (size_t)row * 1024 + off);
            } else if (id < 2048) {
                const int id2 = id - 1024;
                const int row = id2 >> 4, off = (id2 & 15) * 16;
                cp16(stb + FL_KL + row * 272 + off, klg + (size_t)row * 1024 + off);
            } else {
                const int id2 = id - 2048;
                const int row = id2 >> 5, off = (id2 & 31) * 16;
                cp16(stb + FL_V + row * 544 + off, vg + (size_t)row * 2048 + off);
            }
        }
        cp_commit();
    };

    const int kbmax = 2 * qb + 1;
    issue_kv(0, 0);
    issue_kv(1, 1);

    float oacc[16][4];
#pragma unroll
    for (int i = 0; i < 16; i++)
#pragma unroll
        for (int c = 0; c < 4; c++) oacc[i][c] = 0.f;
    float m0 = -1e30f, m1 = -1e30f, l0 = 0.f, l1 = 0.f;

    const int arow = w * 16 + r4;
    const int rg0 = qb * QB + arow;
    const int rg1 = rg0 + 8;

    const char* aH = smc + arow * 272 + q4 * 4;
    const char* aL = smc + FL_QL + arow * 272 + q4 * 4;

    for (int kb = 0; kb <= kbmax; kb++) {
        if (kb < kbmax) cp_wait<1>(); else cp_wait<0>();
        __syncthreads();

        const int cur = kb & 1;
        const char* Khp = smc + FL_ST + (size_t)cur * FL_STSZ;
        const char* Klp = Khp + FL_KL;
        const float* Vsp = (const float*)(Khp + FL_V);

        float sacc[8][4];
#pragma unroll
        for (int nt = 0; nt < 8; nt++)
#pragma unroll
            for (int c = 0; c < 4; c++) sacc[nt][c] = 0.f;

#pragma unroll
        for (int kt = 0; kt < 8; kt++) {
            const int ko = kt * 32;
            uint32_t ah[4], al[4];
            ah[0] = *(const uint32_t*)(aH + ko);
            ah[1] = *(const uint32_t*)(aH + ko + 8 * 272);
            ah[2] = *(const uint32_t*)(aH + ko + 16);
            ah[3] = *(const uint32_t*)(aH + ko + 8 * 272 + 16);
            al[0] = *(const uint32_t*)(aL + ko);
            al[1] = *(const uint32_t*)(aL + ko + 8 * 272);
            al[2] = *(const uint32_t*)(aL + ko + 16);
            al[3] = *(const uint32_t*)(aL + ko + 8 * 272 + 16);
#pragma unroll
            for (int nt = 0; nt < 8; nt++) {
                const char* bp = Khp + (nt * 8 + r4) * 272 + q4 * 4 + ko;
                const char* bq = Klp + (nt * 8 + r4) * 272 + q4 * 4 + ko;
                const uint32_t bh0 = *(const uint32_t*)bp;
                const uint32_t bh1 = *(const uint32_t*)(bp + 16);
                const uint32_t bl0 = *(const uint32_t*)bq;
                const uint32_t bl1 = *(const uint32_t*)(bq + 16);
                mma_bf16(sacc[nt], ah, bh0, bh1);
                mma_bf16(sacc[nt], al, bh0, bh1);
                mma_bf16(sacc[nt], ah, bl0, bl1);
            }
        }

        if (kb >= 2 * qb) {
            const int colb = kb * KB + 2 * q4;
#pragma unroll
            for (int nt = 0; nt < 8; nt++) {
                const int c0 = colb + nt * 8;
                if (c0 > rg0)     sacc[nt][0] = -1e30f;
                if (c0 + 1 > rg0) sacc[nt][1] = -1e30f;
                if (c0 > rg1)     sacc[nt][2] = -1e30f;
                if (c0 + 1 > rg1) sacc[nt][3] = -1e30f;
            }
        }
        float mb0 = -1e30f, mb1 = -1e30f;
#pragma unroll
        for (int nt = 0; nt < 8; nt++) {
            mb0 = fmaxf(mb0, fmaxf(sacc[nt][0], sacc[nt][1]));
            mb1 = fmaxf(mb1, fmaxf(sacc[nt][2], sacc[nt][3]));
        }
        mb0 = fmaxf(mb0, __shfl_xor_sync(0xffffffffu, mb0, 1));
        mb0 = fmaxf(mb0, __shfl_xor_sync(0xffffffffu, mb0, 2));
        mb1 = fmaxf(mb1, __shfl_xor_sync(0xffffffffu, mb1, 1));
        mb1 = fmaxf(mb1, __shfl_xor_sync(0xffffffffu, mb1, 2));

        const float mn0 = fmaxf(m0, mb0), mn1 = fmaxf(m1, mb1);
        const float a0 = __expf(m0 - mn0), a1 = __expf(m1 - mn1);
        m0 = mn0; m1 = mn1;

        float ls0 = 0.f, ls1 = 0.f;
#pragma unroll
        for (int nt = 0; nt < 8; nt++) {
            float p0 = to_tf32(__expf(sacc[nt][0] - mn0));
            float p1 = to_tf32(__expf(sacc[nt][1] - mn0));
            float p2 = to_tf32(__expf(sacc[nt][2] - mn1));
            float p3 = to_tf32(__expf(sacc[nt][3] - mn1));
            sacc[nt][0] = p0; sacc[nt][1] = p1;
            sacc[nt][2] = p2; sacc[nt][3] = p3;
            ls0 += p0 + p1; ls1 += p2 + p3;
        }
        ls0 += __shfl_xor_sync(0xffffffffu, ls0, 1);
        ls0 += __shfl_xor_sync(0xffffffffu, ls0, 2);
        ls1 += __shfl_xor_sync(0xffffffffu, ls1, 1);
        ls1 += __shfl_xor_sync(0xffffffffu, ls1, 2);
        l0 = l0 * a0 + ls0;
        l1 = l1 * a1 + ls1;

#pragma unroll
        for (int nt2 = 0; nt2 < 16; nt2++) {
            oacc[nt2][0] *= a0; oacc[nt2][1] *= a0;
            oacc[nt2][2] *= a1; oacc[nt2][3] *= a1;
        }

        const int src0 = (lane & ~3) | (q4 >> 1);
        const int src1 = src0 | 2;
        const bool oddq = (q4 & 1);
#pragma unroll
        for (int kt2 = 0; kt2 < 8; kt2++) {
            const float t00 = __shfl_sync(0xffffffffu, sacc[kt2][0], src0);
            const float t01 = __shfl_sync(0xffffffffu, sacc[kt2][1], src0);
            const float t02 = __shfl_sync(0xffffffffu, sacc[kt2][2], src0);
            const float t03 = __shfl_sync(0xffffffffu, sacc[kt2][3], src0);
            const float t10 = __shfl_sync(0xffffffffu, sacc[kt2][0], src1);
            const float t11 = __shfl_sync(0xffffffffu, sacc[kt2][1], src1);
            const float t12 = __shfl_sync(0xffffffffu, sacc[kt2][2], src1);
            const float t13 = __shfl_sync(0xffffffffu, sacc[kt2][3], src1);
            float pa[4];
            pa[0] = oddq ? t01 : t00;
            pa[1] = oddq ? t03 : t02;
            pa[2] = oddq ? t11 : t10;
            pa[3] = oddq ? t13 : t12;
            const float* vrow = Vsp + (kt2 * 8 + q4) * LDV + r4;
#pragma unroll
            for (int nt2 = 0; nt2 < 16; nt2++) {
                mma_tf32f(oacc[nt2], pa, vrow[nt2 * 8], vrow[nt2 * 8 + 4 * LDV]);
            }
        }

        __syncthreads();
        if (kb + 2 <= kbmax) issue_kv(kb + 2, cur);
    }

    const float inv0 = 1.f / l0, inv1 = 1.f / l1;
    float* o0 = O + (((size_t)b * SEQ + rg0) * NH + h) * HD;
    float* o1 = O + (((size_t)b * SEQ + rg1) * NH + h) * HD;
#pragma unroll
    for (int nt2 = 0; nt2 < 16; nt2++) {
        const int col = nt2 * 8 + 2 * q4;
        *(float2*)(o0 + col) = make_float2(to_tf32(oacc[nt2][0] * inv0),
                                           to_tf32(oacc[nt2][1] * inv0));
        *(float2*)(o1 + col) = make_float2(to_tf32(oacc[nt2][2] * inv1),
                                           to_tf32(oacc[nt2][3] * inv1));
    }
}

// ---------------------------------------------------------------------------
extern "C" void kernel_launch(void* const* d_in, const int* in_sizes, int n_in,
                              void* d_out, int out_size)
{
    const float* hs   = (const float*)d_in[0];
    const float* cosT = (const float*)d_in[1];
    const float* sinT = (const float*)d_in[2];
    const float* q_w = (const float*)d_in[4];
    const float* q_b = (const float*)d_in[5];
    const float* k_w = (const float*)d_in[6];
    const float* k_b = (const float*)d_in[7];
    const float* v_w = (const float*)d_in[8];
    const float* v_b = (const float*)d_in[9];
    const float* o_w = (const float*)d_in[10];
    float* out = (float*)d_out;

    float *Qb, *Kb, *Vb, *Ab, *HSr, *QWr, *KWr, *VWr, *OWr;
    __nv_bfloat16 *Qhi, *Qlo, *Khi, *Klo;
    cudaGetSymbolAddress((void**)&Qb, g_Q);
    cudaGetSymbolAddress((void**)&Kb, g_K);
    cudaGetSymbolAddress((void**)&Vb, g_V);
    cudaGetSymbolAddress((void**)&Ab, g_A);
    cudaGetSymbolAddress((void**)&HSr, g_HSr);
    cudaGetSymbolAddress((void**)&QWr, g_QWr);
    cudaGetSymbolAddress((void**)&KWr, g_KWr);
    cudaGetSymbolAddress((void**)&VWr, g_VWr);
    cudaGetSymbolAddress((void**)&OWr, g_OWr);
    cudaGetSymbolAddress((void**)&Qhi, g_Qhi);
    cudaGetSymbolAddress((void**)&Qlo, g_Qlo);
    cudaGetSymbolAddress((void**)&Khi, g_Khi);
    cudaGetSymbolAddress((void**)&Klo, g_Klo);

    static cudaStream_t sK = nullptr, sV = nullptr;
    static cudaEvent_t eFork = nullptr, eHS = nullptr, eQW = nullptr,
                       eK = nullptr, eV = nullptr, eOW = nullptr;
    if (!sK) {
        cudaStreamCreateWithFlags(&sK, cudaStreamNonBlocking);
        cudaStreamCreateWithFlags(&sV, cudaStreamNonBlocking);
        cudaEventCreateWithFlags(&eFork, cudaEventDisableTiming);
        cudaEventCreateWithFlags(&eHS, cudaEventDisableTiming);
        cudaEventCreateWithFlags(&eQW, cudaEventDisableTiming);
        cudaEventCreateWithFlags(&eK, cudaEventDisableTiming);
        cudaEventCreateWithFlags(&eV, cudaEventDisableTiming);
        cudaEventCreateWithFlags(&eOW, cudaEventDisableTiming);
        cudaFuncSetAttribute(flash_tc, cudaFuncAttributeMaxDynamicSharedMemorySize, FL_SMEM);
    }

    const int nt = 256;

    // Fork FIRST (capture-legal): side streams join via event from origin.
    cudaEventRecord(eFork, 0);
    cudaStreamWaitEvent(sK, eFork, 0);
    cudaStreamWaitEvent(sV, eFork, 0);

    // sK: round QW -> signal; round KW
    {
        const int n4q = HID * HID / 4;
        round_tf32_k<<<(n4q + nt - 1) / nt, nt, 0, sK>>>((const float4*)q_w, (float4*)QWr, n4q);
        cudaEventRecord(eQW, sK);
        const int n4k = KV_HID * HID / 4;
        round_tf32_k<<<(n4k + nt - 1) / nt, nt, 0, sK>>>((const float4*)k_w, (float4*)KWr, n4k);
    }

    // sV: round VW
    {
        const int n4v = KV_HID * HID / 4;
        round_tf32_k<<<(n4v + nt - 1) / nt, nt, 0, sV>>>((const float4*)v_w, (float4*)VWr, n4v);
    }

    // main: round HS (everyone needs it)
    {
        const int n4 = M_ROWS * HID / 4;
        round_tf32_k<<<(n4 + nt - 1) / nt, nt>>>((const float4*)hs, (float4*)HSr, n4);
        cudaEventRecord(eHS, 0);
    }
    cudaStreamWaitEvent(sK, eHS, 0);
    cudaStreamWaitEvent(sV, eHS, 0);

    // main: Q-proj (needs QW)
    cudaStreamWaitEvent(0, eQW, 0);
    tf32_gemm_nt<<<dim3(HID / 128, M_ROWS / 128), 256, 0, 0>>>(
        HSr, QWr, q_b, Qb, M_ROWS, HID, HID, 0);

    // sK: K-proj
    tf32_gemm_nt<<<dim3(KV_HID / 128, M_ROWS / 128), 256, 0, sK>>>(
        HSr, KWr, k_b, Kb, M_ROWS, KV_HID, HID, 0);
    cudaEventRecord(eK, sK);

    // sV: V-proj (tf32-rounded output), then round OW (overlaps rope+flash)
    tf32_gemm_nt<<<dim3(KV_HID / 128, M_ROWS / 128), 256, 0, sV>>>(
        HSr, VWr, v_b, Vb, M_ROWS, KV_HID, HID, 1);
    cudaEventRecord(eV, sV);
    {
        const int n4 = HID * HID / 4;
        round_tf32_k<<<(n4 + nt - 1) / nt, nt, 0, sV>>>((const float4*)o_w, (float4*)OWr, n4);
    }
    cudaEventRecord(eOW, sV);

    // Join K,V for rope
    cudaStreamWaitEvent(0, eK, 0);
    cudaStreamWaitEvent(0, eV, 0);

    // RoPE + bf16 hi/lo split
    rope_split<<<(BATCH * SEQ * 32 * 64) / 256, 256>>>(
        Qb, Kb, cosT, sinT, Qhi, Qlo, Khi, Klo);

    // Flash attention (single launch, epilogue writes tf32-rounded A)
    flash_tc<<<dim3(SEQ / QB, NH, BATCH), 256, FL_SMEM>>>(
        Qhi, Qlo, Khi, Klo, Vb, Ab);

    // Output projection
    cudaStreamWaitEvent(0, eOW, 0);
    tf32_gemm_nt<<<dim3(HID / 128, M_ROWS / 128), 256>>>(
        Ab, OWr, nullptr, out, M_ROWS, HID, HID, 0);
}

// round 13
// speedup vs baseline: 1.1643x; 1.0010x over previous
#include <cuda_runtime.h>
#include <cuda_bf16.h>
#include <cstdint>

// Problem constants
#define BATCH 2
#define SEQ 2048
#define HID 3584
#define NH 28
#define NKV 4
#define HD 128
#define NREP 7
#define M_ROWS (BATCH * SEQ)           // 4096
#define KV_HID (NKV * HD)              // 512
#define SCALE_F 0.08838834764831845f   // 128^-0.5

// Scratch (device globals; allocation is forbidden)
__device__ float g_Q[(size_t)M_ROWS * HID];
__device__ float g_K[(size_t)M_ROWS * KV_HID];
__device__ float g_V[(size_t)M_ROWS * KV_HID];
__device__ float g_A[(size_t)M_ROWS * HID];
__device__ __nv_bfloat16 g_Qhi[(size_t)M_ROWS * HID];
__device__ __nv_bfloat16 g_Qlo[(size_t)M_ROWS * HID];
__device__ __nv_bfloat16 g_Khi[(size_t)M_ROWS * KV_HID];
__device__ __nv_bfloat16 g_Klo[(size_t)M_ROWS * KV_HID];
// tf32-rounded (rna) copies
__device__ float g_HSr[(size_t)M_ROWS * HID];
__device__ float g_QWr[(size_t)HID * HID];
__device__ float g_KWr[(size_t)KV_HID * HID];
__device__ float g_VWr[(size_t)KV_HID * HID];
__device__ float g_OWr[(size_t)HID * HID];

// ---------------------------------------------------------------------------
// Helpers
// ---------------------------------------------------------------------------
__device__ __forceinline__ float to_tf32(float x) {
    asm("cvt.rna.tf32.f32 %0, %0;" : "+f"(x));
    return x;
}
__device__ __forceinline__ void ldmx4(uint32_t& r0, uint32_t& r1, uint32_t& r2,
                                      uint32_t& r3, uint32_t addr) {
    asm volatile("ldmatrix.sync.aligned.m8n8.x4.shared.b16 {%0,%1,%2,%3}, [%4];"
                 : "=r"(r0), "=r"(r1), "=r"(r2), "=r"(r3) : "r"(addr));
}
__device__ __forceinline__ void mma_tf32(float* c, const uint32_t* a,
                                         uint32_t b0, uint32_t b1) {
    asm volatile(
        "mma.sync.aligned.m16n8k8.row.col.f32.tf32.tf32.f32 "
        "{%0,%1,%2,%3}, {%4,%5,%6,%7}, {%8,%9}, {%0,%1,%2,%3};"
        : "+f"(c[0]), "+f"(c[1]), "+f"(c[2]), "+f"(c[3])
        : "r"(a[0]), "r"(a[1]), "r"(a[2]), "r"(a[3]), "r"(b0), "r"(b1));
}
__device__ __forceinline__ void mma_tf32f(float* c, const float* a,
                                          float b0f, float b1f) {
    uint32_t a0 = __float_as_uint(a[0]), a1 = __float_as_uint(a[1]);
    uint32_t a2 = __float_as_uint(a[2]), a3 = __float_as_uint(a[3]);
    uint32_t b0 = __float_as_uint(b0f), b1 = __float_as_uint(b1f);
    asm volatile(
        "mma.sync.aligned.m16n8k8.row.col.f32.tf32.tf32.f32 "
        "{%0,%1,%2,%3}, {%4,%5,%6,%7}, {%8,%9}, {%0,%1,%2,%3};"
        : "+f"(c[0]), "+f"(c[1]), "+f"(c[2]), "+f"(c[3])
        : "r"(a0), "r"(a1), "r"(a2), "r"(a3), "r"(b0), "r"(b1));
}
__device__ __forceinline__ void mma_bf16(float* c, const uint32_t* a,
                                         uint32_t b0, uint32_t b1) {
    asm volatile(
        "mma.sync.aligned.m16n8k16.row.col.f32.bf16.bf16.f32 "
        "{%0,%1,%2,%3}, {%4,%5,%6,%7}, {%8,%9}, {%0,%1,%2,%3};"
        : "+f"(c[0]), "+f"(c[1]), "+f"(c[2]), "+f"(c[3])
        : "r"(a[0]), "r"(a[1]), "r"(a[2]), "r"(a[3]), "r"(b0), "r"(b1));
}
__device__ __forceinline__ void cp16(uint32_t dst, const void* src) {
    asm volatile("cp.async.cg.shared.global [%0], [%1], 16;" :: "r"(dst), "l"(src));
}
__device__ __forceinline__ void cp_commit() {
    asm volatile("cp.async.commit_group;");
}
template <int N>
__device__ __forceinline__ void cp_wait() {
    asm volatile("cp.async.wait_group %0;" :: "n"(N));
}
__device__ __forceinline__ void bsplit(float x, __nv_bfloat16& hi, __nv_bfloat16& lo) {
    hi = __float2bfloat16(x);
    lo = __float2bfloat16(x - __bfloat162float(hi));
}

// ---------------------------------------------------------------------------
// Elementwise tf32 (rna) rounding pass
// ---------------------------------------------------------------------------
__global__ void round_tf32_k(const float4* __restrict__ in, float4* __restrict__ out, int n4)
{
    const int i = blockIdx.x * blockDim.x + threadIdx.x;
    if (i < n4) {
        float4 v = in[i];
        v.x = to_tf32(v.x); v.y = to_tf32(v.y);
        v.z = to_tf32(v.z); v.w = to_tf32(v.w);
        out[i] = v;
    }
}

// ---------------------------------------------------------------------------
// TF32 tensor-core GEMM: C[M,N] = A[M,K] @ W[N,K]^T + bias
// Inputs PRE-ROUNDED to tf32 — NO cvt in the inner loop (R8/R12 config).
// 128x128 tile, BK=16, 256 threads, 3-stage cp.async, 2 CTAs/SM.
// ---------------------------------------------------------------------------
#define LDA 20
#define BUF_FLOATS (128 * LDA)
#define BUF_BYTES (BUF_FLOATS * 4)

__global__ void __launch_bounds__(256, 2) tf32_gemm_nt(
    const float* __restrict__ A, const float* __restrict__ W,
    const float* __restrict__ bias, float* __restrict__ C,
    int M, int N, int K, int rnd)
{
    __shared__ __align__(16) float As[3][BUF_FLOATS];
    __shared__ __align__(16) float Bs[3][BUF_FLOATS];

    const int bm = blockIdx.y * 128;
    const int bn = blockIdx.x * 128;
    const int tid = threadIdx.x;
    const int lane = tid & 31;
    const int wid = tid >> 5;
    const int wm = wid >> 2;
    const int wn = wid & 3;
    const int g = lane >> 3;
    const int lr = lane & 7;

    const uint32_t sA = (uint32_t)__cvta_generic_to_shared(&As[0][0]);
    const uint32_t sB = (uint32_t)__cvta_generic_to_shared(&Bs[0][0]);

    uint32_t aBase[4], bBase[2];
#pragma unroll
    for (int m = 0; m < 4; m++) {
        int row = wm * 64 + m * 16 + lr + (g & 1) * 8;
        int col = (g >> 1) * 4;
        aBase[m] = sA + (row * LDA + col) * 4;
    }
#pragma unroll
    for (int p = 0; p < 2; p++) {
        int row = wn * 32 + p * 16 + lr + (g >> 1) * 8;
        int col = (g & 1) * 4;
        bBase[p] = sB + (row * LDA + col) * 4;
    }

    const int lrow = tid >> 2;
    const int lcol = (tid & 3) << 2;
    const float* Ap = A + (size_t)(bm + lrow) * K + lcol;
    const float* Wp = W + (size_t)(bn + lrow) * K + lcol;
    const uint32_t smoff = (lrow * LDA + lcol) * 4;
    const uint32_t smoff2 = smoff + 64 * LDA * 4;

    auto issue = [&](int t, int s) {
        const uint32_t da = sA + (uint32_t)s * BUF_BYTES;
        const uint32_t db = sB + (uint32_t)s * BUF_BYTES;
        const float* ap = Ap + t * 16;
        const float* wp = Wp + t * 16;
        cp16(da + smoff, ap);
        cp16(da + smoff2, ap + (size_t)64 * K);
        cp16(db + smoff, wp);
        cp16(db + smoff2, wp + (size_t)64 * K);
        cp_commit();
    };

    float acc[4][4][4];
#pragma unroll
    for (int m = 0; m < 4; m++)
#pragma unroll
        for (int n = 0; n < 4; n++)
#pragma unroll
            for (int i = 0; i < 4; i++) acc[m][n][i] = 0.f;

    const int T = K / 16;
    issue(0, 0);
    issue(1, 1);

    for (int t = 0; t < T; t++) {
        if (t + 1 < T) cp_wait<1>(); else cp_wait<0>();
        __syncthreads();
        if (t + 2 < T) issue(t + 2, (t + 2) % 3);

        const uint32_t bufoff = (uint32_t)(t % 3) * BUF_BYTES;
#pragma unroll
        for (int ks = 0; ks < 16; ks += 8) {
            uint32_t afr[4][4];
#pragma unroll
            for (int m = 0; m < 4; m++)
                ldmx4(afr[m][0], afr[m][1], afr[m][2], afr[m][3],
                      aBase[m] + bufoff + ks * 4);
#pragma unroll
            for (int p = 0; p < 2; p++) {
                uint32_t bf0, bf1, bf2, bf3;
                ldmx4(bf0, bf1, bf2, bf3, bBase[p] + bufoff + ks * 4);
#pragma unroll
                for (int m = 0; m < 4; m++) {
                    mma_tf32(acc[m][2 * p + 0], afr[m], bf0, bf1);
                    mma_tf32(acc[m][2 * p + 1], afr[m], bf2, bf3);
                }
            }
        }
    }

#pragma unroll
    for (int m = 0; m < 4; m++) {
        const int row = bm + wm * 64 + m * 16 + (lane >> 2);
#pragma unroll
        for (int n = 0; n < 4; n++) {
            const int col = bn + wn * 32 + n * 8 + (lane & 3) * 2;
            float bx = 0.f, by = 0.f;
            if (bias) { bx = bias[col]; by = bias[col + 1]; }
            float2 v0 = make_float2(acc[m][n][0] + bx, acc[m][n][1] + by);
            float2 v1 = make_float2(acc[m][n][2] + bx, acc[m][n][3] + by);
            if (rnd) {
                v0.x = to_tf32(v0.x); v0.y = to_tf32(v0.y);
                v1.x = to_tf32(v1.x); v1.y = to_tf32(v1.y);
            }
            *(float2*)&C[(size_t)row * N + col] = v0;
            *(float2*)&C[(size_t)(row + 8) * N + col] = v1;
        }
    }
}

// ---------------------------------------------------------------------------
// RoPE + bf16 hi/lo split. Q additionally prescaled by SCALE_F.
// ---------------------------------------------------------------------------
__global__ void rope_split(const float* __restrict__ Q, const float* __restrict__ K,
                           const float* __restrict__ cosT, const float* __restrict__ sinT,
                           __nv_bfloat16* __restrict__ Qh, __nv_bfloat16* __restrict__ Ql,
                           __nv_bfloat16* __restrict__ Kh, __nv_bfloat16* __restrict__ Kl)
{
    const int idx = blockIdx.x * blockDim.x + threadIdx.x;
    const int d = idx & 63;
    const int h = (idx >> 6) & 31;
    const int s = (idx >> 11) & 2047;
    const int b = idx >> 22;

    const float c1 = cosT[s * 128 + d];
    const float s1 = sinT[s * 128 + d];
    const float c2 = cosT[s * 128 + d + 64];
    const float s2 = sinT[s * 128 + d + 64];

    if (h < 28) {
        const size_t base = (((size_t)b * SEQ + s) * NH + h) * HD;
        const float x1 = Q[base + d];
        const float x2 = Q[base + d + 64];
        const float r1 = (x1 * c1 - x2 * s1) * SCALE_F;
        const float r2 = (x2 * c2 + x1 * s2) * SCALE_F;
        __nv_bfloat16 hi, lo;
        bsplit(r1, hi, lo); Qh[base + d] = hi; Ql[base + d] = lo;
        bsplit(r2, hi, lo); Qh[base + d + 64] = hi; Ql[base + d + 64] = lo;
    } else {
        const size_t base = (((size_t)b * SEQ + s) * NKV + (h - 28)) * HD;
        const float x1 = K[base + d];
        const float x2 = K[base + d + 64];
        const float r1 = x1 * c1 - x2 * s1;
        const float r2 = x2 * c2 + x1 * s2;
        __nv_bfloat16 hi, lo;
        bsplit(r1, hi, lo); Kh[base + d] = hi; Kl[base + d] = lo;
        bsplit(r2, hi, lo); Kh[base + d + 64] = hi; Kl[base + d + 64] = lo;
    }
}

// ---------------------------------------------------------------------------
// Tensor-core causal flash attention (bf16-split QK + tf32 PV).
// QK fragments via ldmatrix.x4 (same words/order as scalar — bit-identical,
// 4x fewer shared-load instructions). Single launch; longest-first order.
// ---------------------------------------------------------------------------
#define QB 128
#define KB 64
#define FL_QL 34816
#define FL_ST 69632
#define FL_STSZ 69632
#define FL_KL 17408
#define FL_V  34816
#define FL_SMEM 208896
#define LDV 136

__global__ void __launch_bounds__(256, 1) flash_tc(
    const __nv_bfloat16* __restrict__ Qh, const __nv_bfloat16* __restrict__ Ql,
    const __nv_bfloat16* __restrict__ Kh, const __nv_bfloat16* __restrict__ Kl,
    const float* __restrict__ V, float* __restrict__ O)
{
    extern __shared__ char smc[];
    const uint32_t sb = (uint32_t)__cvta_generic_to_shared(smc);

    const int qb = gridDim.x - 1 - blockIdx.x;   // longest-first
    const int h = blockIdx.y, b = blockIdx.z;
    const int kvh = h / NREP;
    const int tid = threadIdx.x;
    const int lane = tid & 31;
    const int w = tid >> 5;
    const int q4 = lane & 3;
    const int r4 = lane >> 2;

    {
        const char* qhg = (const char*)(Qh + (((size_t)b * SEQ + (size_t)qb * QB) * NH + h) * HD);
        const char* qlg = (const char*)(Ql + (((size_t)b * SEQ + (size_t)qb * QB) * NH + h) * HD);
#pragma unroll
        for (int i = 0; i < 16; i++) {
            const int id = tid + i * 256;
            if (id < 2048) {
                const int row = id >> 4, off = (id & 15) * 16;
                cp16(sb + row * 272 + off, qhg + (size_t)row * (NH * HD * 2) + off);
            } else {
                const int id2 = id - 2048;
                const int row = id2 >> 4, off = (id2 & 15) * 16;
                cp16(sb + FL_QL + row * 272 + off, qlg + (size_t)row * (NH * HD * 2) + off);
            }
        }
        cp_commit();
    }

    const char* khg0 = (const char*)(Kh + ((size_t)b * SEQ) * KV_HID + kvh * HD);
    const char* klg0 = (const char*)(Kl + ((size_t)b * SEQ) * KV_HID + kvh * HD);
    const char* vg0  = (const char*)(V + ((size_t)b * SEQ) * KV_HID + kvh * HD);

    auto issue_kv = [&](int kb, int s) {
        const uint32_t stb = sb + FL_ST + (uint32_t)s * FL_STSZ;
        const char* khg = khg0 + (size_t)kb * KB * 1024;
        const char* klg = klg0 + (size_t)kb * KB * 1024;
        const char* vg  = vg0 + (size_t)kb * KB * 2048;
#pragma unroll
        for (int i = 0; i < 16; i++) {
            const int id = tid + i * 256;
            if (id < 1024) {
                const int row = id >> 4, off = (id & 15) * 16;
                cp16(stb + row * 272 + off, khg + (size_t)row * 1024 + off);
            } else if (id < 2048) {
                const int id2 = id - 1024;
                const int row = id2 >> 4, off = (id2 & 15) * 16;
                cp16(stb + FL_KL + row * 272 + off, klg + (size_t)row * 1024 + off);
            } else {
                const int id2 = id - 2048;
                const int row = id2 >> 5, off = (id2 & 31) * 16;
                cp16(stb + FL_V + row * 544 + off, vg + (size_t)row * 2048 + off);
            }
        }
        cp_commit();
    };

    const int kbmax = 2 * qb + 1;
    issue_kv(0, 0);
    issue_kv(1, 1);

    float oacc[16][4];
#pragma unroll
    for (int i = 0; i < 16; i++)
#pragma unroll
        for (int c = 0; c < 4; c++) oacc[i][c] = 0.f;
    float m0 = -1e30f, m1 = -1e30f, l0 = 0.f, l1 = 0.f;

    const int arow = w * 16 + r4;
    const int rg0 = qb * QB + arow;
    const int rg1 = rg0 + 8;

    // ---- ldmatrix lane addressing (computed once) ----
    // A (m16k16 frags): mat = lane/8; row = w*16 + (mat&1)*8 + lane%8;
    //                   kbyte = (mat>>1)*16  -> regs {m/klo, m+8/klo, m/khi, m+8/khi}
    const int lmat = lane >> 3;
    const int lrow8 = lane & 7;
    const uint32_t aHl = sb + (uint32_t)(w * 16 + ((lmat & 1) << 3) + lrow8) * 272
                            + (uint32_t)((lmat >> 1) << 4);
    const uint32_t aLl = aHl + FL_QL;
    // B (n8k16 frag pairs): for group p (nt = 2p, 2p+1):
    //   row = (2p + mat/2)*8 + lane%8 ; kbyte = (mat&1)*16
    //   -> regs {b0(nt=2p), b1(nt=2p), b0(nt=2p+1), b1(nt=2p+1)}
    uint32_t bOff[4];
#pragma unroll
    for (int p = 0; p < 4; p++)
        bOff[p] = (uint32_t)((p * 16 + ((lmat >> 1) << 3) + lrow8) * 272)
                + (uint32_t)((lmat & 1) << 4);

    for (int kb = 0; kb <= kbmax; kb++) {
        if (kb < kbmax) cp_wait<1>(); else cp_wait<0>();
        __syncthreads();

        const int cur = kb & 1;
        const uint32_t KhpA = sb + FL_ST + (uint32_t)cur * FL_STSZ;
        const uint32_t KlpA = KhpA + FL_KL;
        const float* Vsp = (const float*)(smc + FL_ST + (size_t)cur * FL_STSZ + FL_V);

        float sacc[8][4];
#pragma unroll
        for (int nt = 0; nt < 8; nt++)
#pragma unroll
            for (int c = 0; c < 4; c++) sacc[nt][c] = 0.f;

#pragma unroll
        for (int kt = 0; kt < 8; kt++) {
            const uint32_t ko = kt * 32;
            uint32_t ah[4], al[4];
            ldmx4(ah[0], ah[1], ah[2], ah[3], aHl + ko);
            ldmx4(al[0], al[1], al[2], al[3], aLl + ko);
#pragma unroll
            for (int p = 0; p < 4; p++) {
                uint32_t h0, h1, h2, h3, L0, L1, L2, L3;
                ldmx4(h0, h1, h2, h3, KhpA + bOff[p] + ko);
                ldmx4(L0, L1, L2, L3, KlpA + bOff[p] + ko);
                mma_bf16(sacc[2 * p + 0], ah, h0, h1);
                mma_bf16(sacc[2 * p + 0], al, h0, h1);
                mma_bf16(sacc[2 * p + 0], ah, L0, L1);
                mma_bf16(sacc[2 * p + 1], ah, h2, h3);
                mma_bf16(sacc[2 * p + 1], al, h2, h3);
                mma_bf16(sacc[2 * p + 1], ah, L2, L3);
            }
        }

        if (kb >= 2 * qb) {
            const int colb = kb * KB + 2 * q4;
#pragma unroll
            for (int nt = 0; nt < 8; nt++) {
                const int c0 = colb + nt * 8;
                if (c0 > rg0)     sacc[nt][0] = -1e30f;
                if (c0 + 1 > rg0) sacc[nt][1] = -1e30f;
                if (c0 > rg1)     sacc[nt][2] = -1e30f;
                if (c0 + 1 > rg1) sacc[nt][3] = -1e30f;
            }
        }
        float mb0 = -1e30f, mb1 = -1e30f;
#pragma unroll
        for (int nt = 0; nt < 8; nt++) {
            mb0 = fmaxf(mb0, fmaxf(sacc[nt][0], sacc[nt][1]));
            mb1 = fmaxf(mb1, fmaxf(sacc[nt][2], sacc[nt][3]));
        }
        mb0 = fmaxf(mb0, __shfl_xor_sync(0xffffffffu, mb0, 1));
        mb0 = fmaxf(mb0, __shfl_xor_sync(0xffffffffu, mb0, 2));
        mb1 = fmaxf(mb1, __shfl_xor_sync(0xffffffffu, mb1, 1));
        mb1 = fmaxf(mb1, __shfl_xor_sync(0xffffffffu, mb1, 2));

        const float mn0 = fmaxf(m0, mb0), mn1 = fmaxf(m1, mb1);
        const float a0 = __expf(m0 - mn0), a1 = __expf(m1 - mn1);
        m0 = mn0; m1 = mn1;

        float ls0 = 0.f, ls1 = 0.f;
#pragma unroll
        for (int nt = 0; nt < 8; nt++) {
            float p0 = to_tf32(__expf(sacc[nt][0] - mn0));
            float p1 = to_tf32(__expf(sacc[nt][1] - mn0));
            float p2 = to_tf32(__expf(sacc[nt][2] - mn1));
            float p3 = to_tf32(__expf(sacc[nt][3] - mn1));
            sacc[nt][0] = p0; sacc[nt][1] = p1;
            sacc[nt][2] = p2; sacc[nt][3] = p3;
            ls0 += p0 + p1; ls1 += p2 + p3;
        }
        ls0 += __shfl_xor_sync(0xffffffffu, ls0, 1);
        ls0 += __shfl_xor_sync(0xffffffffu, ls0, 2);
        ls1 += __shfl_xor_sync(0xffffffffu, ls1, 1);
        ls1 += __shfl_xor_sync(0xffffffffu, ls1, 2);
        l0 = l0 * a0 + ls0;
        l1 = l1 * a1 + ls1;

#pragma unroll
        for (int nt2 = 0; nt2 < 16; nt2++) {
            oacc[nt2][0] *= a0; oacc[nt2][1] *= a0;
            oacc[nt2][2] *= a1; oacc[nt2][3] *= a1;
        }

        const int src0 = (lane & ~3) | (q4 >> 1);
        const int src1 = src0 | 2;
        const bool oddq = (q4 & 1);
#pragma unroll
        for (int kt2 = 0; kt2 < 8; kt2++) {
            const float t00 = __shfl_sync(0xffffffffu, sacc[kt2][0], src0);
            const float t01 = __shfl_sync(0xffffffffu, sacc[kt2][1], src0);
            const float t02 = __shfl_sync(0xffffffffu, sacc[kt2][2], src0);
            const float t03 = __shfl_sync(0xffffffffu, sacc[kt2][3], src0);
            const float t10 = __shfl_sync(0xffffffffu, sacc[kt2][0], src1);
            const float t11 = __shfl_sync(0xffffffffu, sacc[kt2][1], src1);
            const float t12 = __shfl_sync(0xffffffffu, sacc[kt2][2], src1);
            const float t13 = __shfl_sync(0xffffffffu, sacc[kt2][3], src1);
            float pa[4];
            pa[0] = oddq ? t01 : t00;
            pa[1] = oddq ? t03 : t02;
            pa[2] = oddq ? t11 : t10;
            pa[3] = oddq ? t13 : t12;
            const float* vrow = Vsp + (kt2 * 8 + q4) * LDV + r4;
#pragma unroll
            for (int nt2 = 0; nt2 < 16; nt2++) {
                mma_tf32f(oacc[nt2], pa, vrow[nt2 * 8], vrow[nt2 * 8 + 4 * LDV]);
            }
        }

        __syncthreads();
        if (kb + 2 <= kbmax) issue_kv(kb + 2, cur);
    }

    const float inv0 = 1.f / l0, inv1 = 1.f / l1;
    float* o0 = O + (((size_t)b * SEQ + rg0) * NH + h) * HD;
    float* o1 = O + (((size_t)b * SEQ + rg1) * NH + h) * HD;
#pragma unroll
    for (int nt2 = 0; nt2 < 16; nt2++) {
        const int col = nt2 * 8 + 2 * q4;
        *(float2*)(o0 + col) = make_float2(to_tf32(oacc[nt2][0] * inv0),
                                           to_tf32(oacc[nt2][1] * inv0));
        *(float2*)(o1 + col) = make_float2(to_tf32(oacc[nt2][2] * inv1),
                                           to_tf32(oacc[nt2][3] * inv1));
    }
}

// ---------------------------------------------------------------------------
extern "C" void kernel_launch(void* const* d_in, const int* in_sizes, int n_in,
                              void* d_out, int out_size)
{
    const float* hs   = (const float*)d_in[0];
    const float* cosT = (const float*)d_in[1];
    const float* sinT = (const float*)d_in[2];
    const float* q_w = (const float*)d_in[4];
    const float* q_b = (const float*)d_in[5];
    const float* k_w = (const float*)d_in[6];
    const float* k_b = (const float*)d_in[7];
    const float* v_w = (const float*)d_in[8];
    const float* v_b = (const float*)d_in[9];
    const float* o_w = (const float*)d_in[10];
    float* out = (float*)d_out;

    float *Qb, *Kb, *Vb, *Ab, *HSr, *QWr, *KWr, *VWr, *OWr;
    __nv_bfloat16 *Qhi, *Qlo, *Khi, *Klo;
    cudaGetSymbolAddress((void**)&Qb, g_Q);
    cudaGetSymbolAddress((void**)&Kb, g_K);
    cudaGetSymbolAddress((void**)&Vb, g_V);
    cudaGetSymbolAddress((void**)&Ab, g_A);
    cudaGetSymbolAddress((void**)&HSr, g_HSr);
    cudaGetSymbolAddress((void**)&QWr, g_QWr);
    cudaGetSymbolAddress((void**)&KWr, g_KWr);
    cudaGetSymbolAddress((void**)&VWr, g_VWr);
    cudaGetSymbolAddress((void**)&OWr, g_OWr);
    cudaGetSymbolAddress((void**)&Qhi, g_Qhi);
    cudaGetSymbolAddress((void**)&Qlo, g_Qlo);
    cudaGetSymbolAddress((void**)&Khi, g_Khi);
    cudaGetSymbolAddress((void**)&Klo, g_Klo);

    static cudaStream_t sK = nullptr, sV = nullptr;
    static cudaEvent_t eFork = nullptr, eHS = nullptr, eQW = nullptr,
                       eK = nullptr, eV = nullptr, eOW = nullptr;
    if (!sK) {
        cudaStreamCreateWithFlags(&sK, cudaStreamNonBlocking);
        cudaStreamCreateWithFlags(&sV, cudaStreamNonBlocking);
        cudaEventCreateWithFlags(&eFork, cudaEventDisableTiming);
        cudaEventCreateWithFlags(&eHS, cudaEventDisableTiming);
        cudaEventCreateWithFlags(&eQW, cudaEventDisableTiming);
        cudaEventCreateWithFlags(&eK, cudaEventDisableTiming);
        cudaEventCreateWithFlags(&eV, cudaEventDisableTiming);
        cudaEventCreateWithFlags(&eOW, cudaEventDisableTiming);
        cudaFuncSetAttribute(flash_tc, cudaFuncAttributeMaxDynamicSharedMemorySize, FL_SMEM);
    }

    const int nt = 256;

    // Fork FIRST (capture-legal): side streams join via event from origin.
    cudaEventRecord(eFork, 0);
    cudaStreamWaitEvent(sK, eFork, 0);
    cudaStreamWaitEvent(sV, eFork, 0);

    // sK: round QW -> signal; round KW
    {
        const int n4q = HID * HID / 4;
        round_tf32_k<<<(n4q + nt - 1) / nt, nt, 0, sK>>>((const float4*)q_w, (float4*)QWr, n4q);
        cudaEventRecord(eQW, sK);
        const int n4k = KV_HID * HID / 4;
        round_tf32_k<<<(n4k + nt - 1) / nt, nt, 0, sK>>>((const float4*)k_w, (float4*)KWr, n4k);
    }

    // sV: round VW
    {
        const int n4v = KV_HID * HID / 4;
        round_tf32_k<<<(n4v + nt - 1) / nt, nt, 0, sV>>>((const float4*)v_w, (float4*)VWr, n4v);
    }

    // main: round HS (everyone needs it)
    {
        const int n4 = M_ROWS * HID / 4;
        round_tf32_k<<<(n4 + nt - 1) / nt, nt>>>((const float4*)hs, (float4*)HSr, n4);
        cudaEventRecord(eHS, 0);
    }
    cudaStreamWaitEvent(sK, eHS, 0);
    cudaStreamWaitEvent(sV, eHS, 0);

    // main: Q-proj (needs QW)
    cudaStreamWaitEvent(0, eQW, 0);
    tf32_gemm_nt<<<dim3(HID / 128, M_ROWS / 128), 256, 0, 0>>>(
        HSr, QWr, q_b, Qb, M_ROWS, HID, HID, 0);

    // sK: K-proj
    tf32_gemm_nt<<<dim3(KV_HID / 128, M_ROWS / 128), 256, 0, sK>>>(
        HSr, KWr, k_b, Kb, M_ROWS, KV_HID, HID, 0);
    cudaEventRecord(eK, sK);

    // sV: V-proj (tf32-rounded output), then round OW (overlaps rope+flash)
    tf32_gemm_nt<<<dim3(KV_HID / 128, M_ROWS / 128), 256, 0, sV>>>(
        HSr, VWr, v_b, Vb, M_ROWS, KV_HID, HID, 1);
    cudaEventRecord(eV, sV);
    {
        const int n4 = HID * HID / 4;
        round_tf32_k<<<(n4 + nt - 1) / nt, nt, 0, sV>>>((const float4*)o_w, (float4*)OWr, n4);
    }
    cudaEventRecord(eOW, sV);

    // Join K,V for rope
    cudaStreamWaitEvent(0, eK, 0);
    cudaStreamWaitEvent(0, eV, 0);

    // RoPE + bf16 hi/lo split
    rope_split<<<(BATCH * SEQ * 32 * 64) / 256, 256>>>(
        Qb, Kb, cosT, sinT, Qhi, Qlo, Khi, Klo);

    // Flash attention (single launch, epilogue writes tf32-rounded A)
    flash_tc<<<dim3(SEQ / QB, NH, BATCH), 256, FL_SMEM>>>(
        Qhi, Qlo, Khi, Klo, Vb, Ab);

    // Output projection
    cudaStreamWaitEvent(0, eOW, 0);
    tf32_gemm_nt<<<dim3(HID / 128, M_ROWS / 128), 256>>>(
        Ab, OWr, nullptr, out, M_ROWS, HID, HID, 0);
}